// round 4
// baseline (speedup 1.0000x reference)
#include <cuda_runtime.h>

// SplitMLP: out[b,g,o] = b2[g,o] + sum_h W2[g,o,h] * relu( b1[g,h]
//                      + sum_c W1_day[g,h,c]*day[b,c] + sum_v W1_var[g,h,v]*items[b,g,v] )
// B=128, C=16, V=32, H=64, O=4, G=10000. All fp32.

constexpr int B = 128;
constexpr int C = 16;
constexpr int V = 32;
constexpr int H = 64;
constexpr int O = 4;
constexpr int G = 10000;

constexpr int GPB = 8;       // groups per CTA
constexpr int THREADS = 128; // one thread per batch row
constexpr int W1K = C + V;   // 48 fc1 input features
constexpr int W1S = 68;      // smem row stride (floats): 272B = 17*16 -> rows stay 16B aligned, conflicts reduced

// ---- packed f32x2 helpers (ptxas won't auto-fuse; must be PTX) ----
__device__ __forceinline__ unsigned long long ffma2(unsigned long long a,
                                                    unsigned long long b,
                                                    unsigned long long c) {
    unsigned long long d;
    asm("fma.rn.f32x2 %0, %1, %2, %3;" : "=l"(d) : "l"(a), "l"(b), "l"(c));
    return d;
}
__device__ __forceinline__ unsigned long long bcast2(float x) {
    unsigned long long d;
    unsigned xi = __float_as_uint(x);
    asm("mov.b64 %0, {%1, %1};" : "=l"(d) : "r"(xi));
    return d;
}
__device__ __forceinline__ unsigned long long pack2(float x, float y) {
    unsigned long long d;
    unsigned xi = __float_as_uint(x), yi = __float_as_uint(y);
    asm("mov.b64 %0, {%1, %2};" : "=l"(d) : "r"(xi), "r"(yi));
    return d;
}
__device__ __forceinline__ float2 unpack2(unsigned long long a) {
    unsigned xi, yi;
    asm("mov.b64 {%0, %1}, %2;" : "=r"(xi), "=r"(yi) : "l"(a));
    return make_float2(__uint_as_float(xi), __uint_as_float(yi));
}

__global__ void __launch_bounds__(THREADS)
splitmlp_kernel(const float* __restrict__ day,     // [B][C]
                const float* __restrict__ items,   // [B][G][V]
                const float* __restrict__ W1_day,  // [G][H][C]
                const float* __restrict__ W1_var,  // [G][H][V]
                const float* __restrict__ b1,      // [G][H]
                const float* __restrict__ W2,      // [G][O][H]
                const float* __restrict__ b2,      // [G][O]
                float* __restrict__ out)           // [B][G][O]
{
    __shared__ __align__(16) float s_w1[W1K][W1S];     // fc1 weights, k-major transposed
    __shared__ __align__(16) float s_w2[O * H];        // fc2 weights, o-major (gmem layout)
    __shared__ __align__(16) float s_b1[H];
    __shared__ __align__(16) float s_b2[4];
    __shared__ __align__(16) float s_out[B][GPB * O];  // output staging for coalesced store

    const int tid = threadIdx.x;           // = batch row b
    const int g0  = blockIdx.x * GPB;

    // day row -> registers, once per CTA (8KB table, L2-resident)
    float xd[C];
    {
        const float4* dp = reinterpret_cast<const float4*>(day + tid * C);
#pragma unroll
        for (int j = 0; j < C / 4; ++j) {
            float4 v = dp[j];
            xd[4 * j + 0] = v.x; xd[4 * j + 1] = v.y;
            xd[4 * j + 2] = v.z; xd[4 * j + 3] = v.w;
        }
    }

    for (int gg = 0; gg < GPB; ++gg) {
        const int g = g0 + gg;
        __syncthreads();  // previous group's compute done reading smem weights

        // items row: exactly one 128B line per thread; issue LDGs early so the
        // day-part of fc1 later covers their latency
        float xv[V];
        {
            const float4* ip = reinterpret_cast<const float4*>(
                items + ((size_t)tid * G + g) * V);
#pragma unroll
            for (int j = 0; j < V / 4; ++j) {
                float4 v = ip[j];
                xv[4 * j + 0] = v.x; xv[4 * j + 1] = v.y;
                xv[4 * j + 2] = v.z; xv[4 * j + 3] = v.w;
            }
        }

        // ---- cooperative weight load (transpose W1 into [k][h]) ----
        {
            const float4* wd = reinterpret_cast<const float4*>(W1_day + (size_t)g * H * C);
#pragma unroll
            for (int r = 0; r < (H * C) / (4 * THREADS); ++r) {
                int i4 = r * THREADS + tid;
                int f = i4 * 4;
                int h = f >> 4, c = f & (C - 1);
                float4 w = wd[i4];
                s_w1[c + 0][h] = w.x; s_w1[c + 1][h] = w.y;
                s_w1[c + 2][h] = w.z; s_w1[c + 3][h] = w.w;
            }
            const float4* wv = reinterpret_cast<const float4*>(W1_var + (size_t)g * H * V);
#pragma unroll
            for (int r = 0; r < (H * V) / (4 * THREADS); ++r) {
                int i4 = r * THREADS + tid;
                int f = i4 * 4;
                int h = f >> 5, v = f & (V - 1);
                float4 w = wv[i4];
                s_w1[C + v + 0][h] = w.x; s_w1[C + v + 1][h] = w.y;
                s_w1[C + v + 2][h] = w.z; s_w1[C + v + 3][h] = w.w;
            }
            if (tid < (O * H) / 4)
                reinterpret_cast<float4*>(s_w2)[tid] =
                    reinterpret_cast<const float4*>(W2 + (size_t)g * O * H)[tid];
            if (tid < H / 4)
                reinterpret_cast<float4*>(s_b1)[tid] =
                    reinterpret_cast<const float4*>(b1 + (size_t)g * H)[tid];
            if (tid == 0)
                reinterpret_cast<float4*>(s_b2)[0] =
                    reinterpret_cast<const float4*>(b2 + (size_t)g * O)[0];
        }
        __syncthreads();

        // ---- fc1: 32 packed accumulators, acc[m] = h(2m, 2m+1) ----
        unsigned long long acc[H / 2];
        {
            const unsigned long long* b1p = reinterpret_cast<const unsigned long long*>(s_b1);
#pragma unroll
            for (int m = 0; m < H / 2; ++m) acc[m] = b1p[m];
        }
#pragma unroll
        for (int k = 0; k < C; ++k) {
            unsigned long long xb = bcast2(xd[k]);
            const ulonglong2* w = reinterpret_cast<const ulonglong2*>(&s_w1[k][0]);
#pragma unroll
            for (int j = 0; j < H / 4; ++j) {
                ulonglong2 ww = w[j];
                acc[2 * j + 0] = ffma2(ww.x, xb, acc[2 * j + 0]);
                acc[2 * j + 1] = ffma2(ww.y, xb, acc[2 * j + 1]);
            }
        }
#pragma unroll
        for (int k = 0; k < V; ++k) {
            unsigned long long xb = bcast2(xv[k]);
            const ulonglong2* w = reinterpret_cast<const ulonglong2*>(&s_w1[C + k][0]);
#pragma unroll
            for (int j = 0; j < H / 4; ++j) {
                ulonglong2 ww = w[j];
                acc[2 * j + 0] = ffma2(ww.x, xb, acc[2 * j + 0]);
                acc[2 * j + 1] = ffma2(ww.y, xb, acc[2 * j + 1]);
            }
        }

        // ---- ReLU (repack in place) ----
#pragma unroll
        for (int m = 0; m < H / 2; ++m) {
            float2 v = unpack2(acc[m]);
            acc[m] = pack2(fmaxf(v.x, 0.0f), fmaxf(v.y, 0.0f));
        }

        // ---- fc2: y[o] = sum_h relu(h)*W2[o][h] + b2[o] ----
#pragma unroll
        for (int o = 0; o < O; ++o) {
            const ulonglong2* w2p = reinterpret_cast<const ulonglong2*>(&s_w2[o * H]);
            unsigned long long ya = 0ull, yb = 0ull;  // {0.0f, 0.0f}
#pragma unroll
            for (int j = 0; j < H / 4; ++j) {
                ulonglong2 ww = w2p[j];
                ya = ffma2(acc[2 * j + 0], ww.x, ya);
                yb = ffma2(acc[2 * j + 1], ww.y, yb);
            }
            float2 a = unpack2(ya), bsum = unpack2(yb);
            s_out[tid][gg * O + o] = a.x + a.y + bsum.x + bsum.y + s_b2[o];
        }
    }

    __syncthreads();
    // ---- coalesced store: per batch row, 32 contiguous floats = [g0..g0+7] x O ----
#pragma unroll
    for (int r = 0; r < (B * GPB * O) / (4 * THREADS); ++r) {
        int f4 = r * THREADS + tid;
        int bb = f4 >> 3;       // batch row
        int q  = f4 & 7;        // which float4 within that row's 32-float chunk
        reinterpret_cast<float4*>(out)[(size_t)bb * G + g0 + q] =
            reinterpret_cast<const float4*>(&s_out[bb][0])[q];
    }
}

extern "C" void kernel_launch(void* const* d_in, const int* in_sizes, int n_in,
                              void* d_out, int out_size) {
    const float* day    = (const float*)d_in[0];
    const float* items  = (const float*)d_in[1];
    const float* W1_day = (const float*)d_in[2];
    const float* W1_var = (const float*)d_in[3];
    const float* b1     = (const float*)d_in[4];
    const float* W2     = (const float*)d_in[5];
    const float* b2     = (const float*)d_in[6];
    float* out = (float*)d_out;

    splitmlp_kernel<<<G / GPB, THREADS>>>(day, items, W1_day, W1_var, b1, W2, b2, out);
}

// round 7
// speedup vs baseline: 1.4251x; 1.4251x over previous
#include <cuda_runtime.h>

// SplitMLP: out[b,g,o] = b2[g,o] + sum_h W2[g,o,h] * relu( b1[g,h]
//        + sum_c W1_day[g,h,c]*day[b,c] + sum_v W1_var[g,h,v]*items[b,g,v] )
// B=128, C=16, V=32, H=64, O=4, G=10000. fp32.
//
// R5 design: register-tiled GEMM per group. Thread tile = 4 batch rows x 16 hidden.
// x transposed to s_x[k][b], weights to s_w1[k][h]. Per k: 5 conflict-free LDS.128
// feed 32 FFMA2 (vs 16 LDS per 32 in R4 -> L1tex was 86% busy). fc2 via per-thread
// partials + shfl.xor allreduce over the 4-thread h-quad.

constexpr int B = 128;
constexpr int C = 16;
constexpr int V = 32;
constexpr int H = 64;
constexpr int O = 4;
constexpr int G = 10000;

constexpr int GPB = 8;
constexpr int THREADS = 128;
constexpr int KTOT = C + V;   // 48
constexpr int XS = 132;       // s_x row stride (floats): k*132 % 32 = 4k -> aligned, conflict-free
constexpr int WS = 68;        // s_w1/s_w2 row stride

using u64 = unsigned long long;

__device__ __forceinline__ u64 ffma2(u64 a, u64 b, u64 c) {
    u64 d;
    asm("fma.rn.f32x2 %0, %1, %2, %3;" : "=l"(d) : "l"(a), "l"(b), "l"(c));
    return d;
}
__device__ __forceinline__ u64 bcast2(float x) {
    u64 d; unsigned xi = __float_as_uint(x);
    asm("mov.b64 %0, {%1, %1};" : "=l"(d) : "r"(xi));
    return d;
}
__device__ __forceinline__ float2 unpack2(u64 a) {
    unsigned x, y;
    asm("mov.b64 {%0, %1}, %2;" : "=r"(x), "=r"(y) : "l"(a));
    return make_float2(__uint_as_float(x), __uint_as_float(y));
}
__device__ __forceinline__ u64 pack2(float x, float y) {
    u64 d; unsigned xi = __float_as_uint(x), yi = __float_as_uint(y);
    asm("mov.b64 %0, {%1, %2};" : "=l"(d) : "r"(xi), "r"(yi));
    return d;
}

__global__ void __launch_bounds__(THREADS, 4)
splitmlp_kernel(const float* __restrict__ day,     // [B][C]
                const float* __restrict__ items,   // [B][G][V]
                const float* __restrict__ W1_day,  // [G][H][C]
                const float* __restrict__ W1_var,  // [G][H][V]
                const float* __restrict__ b1,      // [G][H]
                const float* __restrict__ W2,      // [G][O][H]
                const float* __restrict__ b2,      // [G][O]
                float* __restrict__ out)           // [B][G][O]
{
    __shared__ __align__(16) float s_x[KTOT][XS];   // x transposed: [k][b]
    __shared__ __align__(16) float s_w1[KTOT][WS];  // fc1 weights:  [k][h]
    __shared__ __align__(16) float s_w2[O][WS];     // fc2 weights:  [o][h]
    __shared__ __align__(16) float s_b1[H];
    __shared__ __align__(16) float s_b2[4];

    const int tid  = threadIdx.x;
    const int lane = tid & 31;
    const int w    = tid >> 5;
    const int tx   = lane & 3;   // h-chunk: h in {tx*8..tx*8+7} u {32+tx*8..32+tx*8+7}
    const int ty   = lane >> 2;  // b-tile:  b in wb + ty*4 + {0..3}
    const int wb   = w * 32;
    const int g0   = blockIdx.x * GPB;

    // ---- day transpose into s_x rows [0,16), once per CTA ----
    {
        const float4* dp = reinterpret_cast<const float4*>(day + tid * C);
#pragma unroll
        for (int j = 0; j < C / 4; ++j) {
            float4 v = dp[j];
            s_x[4 * j + 0][tid] = v.x; s_x[4 * j + 1][tid] = v.y;
            s_x[4 * j + 2][tid] = v.z; s_x[4 * j + 3][tid] = v.w;
        }
    }

    for (int gg = 0; gg < GPB; ++gg) {
        const int g = g0 + gg;

        // ---- stage all LDGs before the barrier (latency hides under sync) ----
        float4 it[8];
        {
            const float4* ip = reinterpret_cast<const float4*>(items + ((size_t)tid * G + g) * V);
#pragma unroll
            for (int j = 0; j < 8; ++j) it[j] = ip[j];
        }
        float4 wd[2];
        {
            const float4* p = reinterpret_cast<const float4*>(W1_day + (size_t)g * H * C);
#pragma unroll
            for (int r = 0; r < 2; ++r) wd[r] = p[r * THREADS + tid];
        }
        float4 wv[4];
        {
            const float4* p = reinterpret_cast<const float4*>(W1_var + (size_t)g * H * V);
#pragma unroll
            for (int r = 0; r < 4; ++r) wv[r] = p[r * THREADS + tid];
        }
        float4 w2r; const bool has_w2 = tid < (O * H) / 4;  // 64 threads
        if (has_w2) w2r = reinterpret_cast<const float4*>(W2 + (size_t)g * O * H)[tid];
        float4 b1r; const bool has_b1 = tid < H / 4;        // 16 threads
        if (has_b1) b1r = reinterpret_cast<const float4*>(b1 + (size_t)g * H)[tid];
        float4 b2r;
        if (tid == 0) b2r = reinterpret_cast<const float4*>(b2 + (size_t)g * O)[0];

        __syncthreads();  // previous group's compute done with smem

        // ---- STS: items transpose (conflict-free scalar columns) ----
#pragma unroll
        for (int j = 0; j < 8; ++j) {
            s_x[C + 4 * j + 0][tid] = it[j].x; s_x[C + 4 * j + 1][tid] = it[j].y;
            s_x[C + 4 * j + 2][tid] = it[j].z; s_x[C + 4 * j + 3][tid] = it[j].w;
        }
        // W1_day -> s_w1[c][h]
#pragma unroll
        for (int r = 0; r < 2; ++r) {
            int i4 = r * THREADS + tid;
            int h = i4 >> 2, c = (i4 << 2) & (C - 1);
            s_w1[c + 0][h] = wd[r].x; s_w1[c + 1][h] = wd[r].y;
            s_w1[c + 2][h] = wd[r].z; s_w1[c + 3][h] = wd[r].w;
        }
        // W1_var -> s_w1[16+v][h]
#pragma unroll
        for (int r = 0; r < 4; ++r) {
            int i4 = r * THREADS + tid;
            int h = i4 >> 3, v = (i4 << 2) & (V - 1);
            s_w1[C + v + 0][h] = wv[r].x; s_w1[C + v + 1][h] = wv[r].y;
            s_w1[C + v + 2][h] = wv[r].z; s_w1[C + v + 3][h] = wv[r].w;
        }
        if (has_w2) {
            int o = tid >> 4, hh = (tid << 2) & (H - 1);
            *reinterpret_cast<float4*>(&s_w2[o][hh]) = w2r;
        }
        if (has_b1) *reinterpret_cast<float4*>(&s_b1[tid * 4]) = b1r;
        if (tid == 0) *reinterpret_cast<float4*>(&s_b2[0]) = b2r;
        __syncthreads();

        // ---- fc1: acc[r][p] packed over h-pairs; init with b1 ----
        u64 acc[4][8];
        {
            ulonglong2 i0 = *reinterpret_cast<const ulonglong2*>(&s_b1[tx * 8]);
            ulonglong2 i1 = *reinterpret_cast<const ulonglong2*>(&s_b1[tx * 8 + 4]);
            ulonglong2 i2 = *reinterpret_cast<const ulonglong2*>(&s_b1[32 + tx * 8]);
            ulonglong2 i3 = *reinterpret_cast<const ulonglong2*>(&s_b1[32 + tx * 8 + 4]);
            u64 q[8] = {i0.x, i0.y, i1.x, i1.y, i2.x, i2.y, i3.x, i3.y};
#pragma unroll
            for (int r = 0; r < 4; ++r)
#pragma unroll
                for (int p = 0; p < 8; ++p) acc[r][p] = q[p];
        }

#pragma unroll 16
        for (int k = 0; k < KTOT; ++k) {
            float4 xv = *reinterpret_cast<const float4*>(&s_x[k][wb + ty * 4]);
            ulonglong2 wA = *reinterpret_cast<const ulonglong2*>(&s_w1[k][tx * 8]);
            ulonglong2 wB = *reinterpret_cast<const ulonglong2*>(&s_w1[k][tx * 8 + 4]);
            ulonglong2 wC = *reinterpret_cast<const ulonglong2*>(&s_w1[k][32 + tx * 8]);
            ulonglong2 wD = *reinterpret_cast<const ulonglong2*>(&s_w1[k][32 + tx * 8 + 4]);
            u64 wp[8] = {wA.x, wA.y, wB.x, wB.y, wC.x, wC.y, wD.x, wD.y};
            u64 xb[4] = {bcast2(xv.x), bcast2(xv.y), bcast2(xv.z), bcast2(xv.w)};
#pragma unroll
            for (int r = 0; r < 4; ++r)
#pragma unroll
                for (int p = 0; p < 8; ++p)
                    acc[r][p] = ffma2(wp[p], xb[r], acc[r][p]);
        }

        // ---- ReLU (packed, via unpack/fmax/pack) ----
#pragma unroll
        for (int r = 0; r < 4; ++r)
#pragma unroll
            for (int p = 0; p < 8; ++p) {
                float2 v = unpack2(acc[r][p]);
                acc[r][p] = pack2(fmaxf(v.x, 0.0f), fmaxf(v.y, 0.0f));
            }

        // ---- fc2: per-thread partial over its 16 h, packed ----
        float y[4][4];
#pragma unroll
        for (int o = 0; o < 4; ++o) {
            ulonglong2 a  = *reinterpret_cast<const ulonglong2*>(&s_w2[o][tx * 8]);
            ulonglong2 b_ = *reinterpret_cast<const ulonglong2*>(&s_w2[o][tx * 8 + 4]);
            ulonglong2 c_ = *reinterpret_cast<const ulonglong2*>(&s_w2[o][32 + tx * 8]);
            ulonglong2 d_ = *reinterpret_cast<const ulonglong2*>(&s_w2[o][32 + tx * 8 + 4]);
            u64 wq[8] = {a.x, a.y, b_.x, b_.y, c_.x, c_.y, d_.x, d_.y};
#pragma unroll
            for (int r = 0; r < 4; ++r) {
                u64 ps = 0ull;
#pragma unroll
                for (int p = 0; p < 8; ++p) ps = ffma2(acc[r][p], wq[p], ps);
                float2 v = unpack2(ps);
                y[r][o] = v.x + v.y;
            }
        }

        // ---- allreduce over the tx-quad (h-chunks) ----
#pragma unroll
        for (int r = 0; r < 4; ++r)
#pragma unroll
            for (int o = 0; o < 4; ++o) {
                y[r][o] += __shfl_xor_sync(0xffffffffu, y[r][o], 1);
                y[r][o] += __shfl_xor_sync(0xffffffffu, y[r][o], 2);
            }

        float4 bb = *reinterpret_cast<const float4*>(&s_b2[0]);
        const int brow = wb + ty * 4 + tx;  // lane tx writes its r==tx row
        float4 o4;
        if (tx == 0)
            o4 = make_float4(y[0][0] + bb.x, y[0][1] + bb.y, y[0][2] + bb.z, y[0][3] + bb.w);
        else if (tx == 1)
            o4 = make_float4(y[1][0] + bb.x, y[1][1] + bb.y, y[1][2] + bb.z, y[1][3] + bb.w);
        else if (tx == 2)
            o4 = make_float4(y[2][0] + bb.x, y[2][1] + bb.y, y[2][2] + bb.z, y[2][3] + bb.w);
        else
            o4 = make_float4(y[3][0] + bb.x, y[3][1] + bb.y, y[3][2] + bb.z, y[3][3] + bb.w);

        reinterpret_cast<float4*>(out)[(size_t)brow * G + g] = o4;
    }
}

extern "C" void kernel_launch(void* const* d_in, const int* in_sizes, int n_in,
                              void* d_out, int out_size) {
    const float* day    = (const float*)d_in[0];
    const float* items  = (const float*)d_in[1];
    const float* W1_day = (const float*)d_in[2];
    const float* W1_var = (const float*)d_in[3];
    const float* b1     = (const float*)d_in[4];
    const float* W2     = (const float*)d_in[5];
    const float* b2     = (const float*)d_in[6];
    float* out = (float*)d_out;

    splitmlp_kernel<<<G / GPB, THREADS>>>(day, items, W1_day, W1_var, b1, W2, b2, out);
}